// round 1
// baseline (speedup 1.0000x reference)
#include <cuda_runtime.h>

// LambdaRankLoss, N=8192, 5 integer target classes (0..4), SIGMA=1.
//
// Math restructuring vs reference:
//   rank_i       = prefix_count(class < v_i) + stable_occurrence(i within class) + 1
//   decay_i      = 1/log2(rank_i+1),  gain_i = 2^t_i,  e_i = exp(SIGMA*p_i)
//   sig_ij       = 1/(1+exp(sigma(p_i-p_j))) = e_j/(e_i+e_j)
//   |Ninv*gain_diff*decay_diff| = Ninv*(g_j-g_i)*(dec_i-dec_j)   (>=0, 0 for ties)
//   0.5*(1-Sij)  = (t_j > t_i) ? 1 : 0   (don't-care on ties: weight is 0)
//   lambda_i = SIGMA*Ninv * sum_j (c_ij - sig_ij)*(g_j-g_i)*(dec_i-dec_j)

#define N            8192
#define NCLASS       5
#define SIGMA_F      1.0f
#define K_DCG        512

#define PREP_THREADS 1024
#define CHUNK        (N / PREP_THREADS)      // 8

#define PAIR_THREADS 256
#define ROWS_PER_BLK 512                     // 2 rows per thread
#define RB           (N / ROWS_PER_BLK)      // 16 row blocks
#define NJS          32                      // j slices
#define JTILE        (N / NJS)               // 256

// scratch (device globals; no allocation allowed)
__device__ float4 g_egd[N];                  // (e, gain, decay, 0)
__device__ float  g_scale;                   // SIGMA * Ninv
__device__ float  g_partial[NJS][N];

// ---------------------------------------------------------------------------
// Prep: class counts, stable ranks, decay, gains, exp(pred), maxDCG -> scale.
// Single block, 1024 threads, chunked stable per-class scan.
// ---------------------------------------------------------------------------
__global__ void __launch_bounds__(PREP_THREADS)
prep_kernel(const float* __restrict__ pred, const float* __restrict__ tgt) {
    __shared__ int   s_chunk[NCLASS][PREP_THREADS];
    __shared__ float s_red[K_DCG];
    __shared__ int   s_tot[NCLASS];

    const int t    = threadIdx.x;
    const int base = t * CHUNK;

    int   loc[NCLASS] = {0, 0, 0, 0, 0};
    float tv[CHUNK];

    #pragma unroll
    for (int k = 0; k < CHUNK; k++) {
        float tval = tgt[base + k];
        tv[k] = tval;
        int v = (int)tval;
        if (v < 0) v = 0;
        if (v > NCLASS - 1) v = NCLASS - 1;
        loc[v]++;
        float e = __expf(SIGMA_F * pred[base + k]);
        float g = exp2f(tval);
        g_egd[base + k].x = e;
        g_egd[base + k].y = g;
        g_egd[base + k].w = 0.0f;
    }
    #pragma unroll
    for (int v = 0; v < NCLASS; v++) s_chunk[v][t] = loc[v];
    __syncthreads();

    // inclusive Hillis-Steele scan across threads, per class
    for (int ofs = 1; ofs < PREP_THREADS; ofs <<= 1) {
        int add[NCLASS];
        #pragma unroll
        for (int v = 0; v < NCLASS; v++)
            add[v] = (t >= ofs) ? s_chunk[v][t - ofs] : 0;
        __syncthreads();
        #pragma unroll
        for (int v = 0; v < NCLASS; v++) s_chunk[v][t] += add[v];
        __syncthreads();
    }
    if (t == 0) {
        #pragma unroll
        for (int v = 0; v < NCLASS; v++) s_tot[v] = s_chunk[v][PREP_THREADS - 1];
    }
    __syncthreads();

    int tot[NCLASS], prefix[NCLASS];
    {
        int run = 0;
        #pragma unroll
        for (int v = 0; v < NCLASS; v++) { tot[v] = s_tot[v]; prefix[v] = run; run += tot[v]; }
    }

    // stable occurrence index -> rank -> decay
    int occ[NCLASS];
    #pragma unroll
    for (int v = 0; v < NCLASS; v++) occ[v] = s_chunk[v][t] - loc[v];
    #pragma unroll
    for (int k = 0; k < CHUNK; k++) {
        int v = (int)tv[k];
        if (v < 0) v = 0;
        if (v > NCLASS - 1) v = NCLASS - 1;
        int rank = prefix[v] + occ[v] + 1;
        occ[v]++;
        g_egd[base + k].z = __fdividef(1.0f, log2f((float)rank + 1.0f));
    }

    // maxDCG over top K_DCG of descending-sorted targets
    if (t < K_DCG) {
        int k  = t + 1;
        int c4 = tot[4];
        int c3 = c4 + tot[3];
        int c2 = c3 + tot[2];
        int c1 = c2 + tot[1];
        int v  = (k <= c4) ? 4 : (k <= c3) ? 3 : (k <= c2) ? 2 : (k <= c1) ? 1 : 0;
        s_red[t] = (exp2f((float)v) - 1.0f) / log2f((float)k + 1.0f);
    }
    __syncthreads();
    for (int s = K_DCG / 2; s > 0; s >>= 1) {
        if (t < s) s_red[t] += s_red[t + s];
        __syncthreads();
    }
    if (t == 0) g_scale = SIGMA_F * __fdividef(1.0f, s_red[0]);
}

// ---------------------------------------------------------------------------
// Pairwise kernel: grid (RB, NJS). Each thread owns 2 rows, loops over a
// JTILE slice of j. Per-warp j loads are uniform -> LDG.128 broadcast.
// ---------------------------------------------------------------------------
__global__ void __launch_bounds__(PAIR_THREADS)
pair_kernel() {
    const int t    = threadIdx.x;
    const int row0 = blockIdx.x * ROWS_PER_BLK + t;
    const int row1 = row0 + PAIR_THREADS;

    const float4 a0 = g_egd[row0];
    const float4 a1 = g_egd[row1];
    const float4* __restrict__ p = g_egd + blockIdx.y * JTILE;

    float acc0 = 0.0f, acc1 = 0.0f, acc0b = 0.0f, acc1b = 0.0f;

    #pragma unroll 4
    for (int j = 0; j < JTILE; j += 2) {
        const float4 b0 = __ldg(p + j);
        const float4 b1 = __ldg(p + j + 1);
        {
            float s = __fdividef(b0.x, a0.x + b0.x);
            float c = (b0.y > a0.y) ? 1.0f : 0.0f;
            float w = (b0.y - a0.y) * (a0.z - b0.z);
            acc0 = fmaf(c - s, w, acc0);
        }
        {
            float s = __fdividef(b0.x, a1.x + b0.x);
            float c = (b0.y > a1.y) ? 1.0f : 0.0f;
            float w = (b0.y - a1.y) * (a1.z - b0.z);
            acc1 = fmaf(c - s, w, acc1);
        }
        {
            float s = __fdividef(b1.x, a0.x + b1.x);
            float c = (b1.y > a0.y) ? 1.0f : 0.0f;
            float w = (b1.y - a0.y) * (a0.z - b1.z);
            acc0b = fmaf(c - s, w, acc0b);
        }
        {
            float s = __fdividef(b1.x, a1.x + b1.x);
            float c = (b1.y > a1.y) ? 1.0f : 0.0f;
            float w = (b1.y - a1.y) * (a1.z - b1.z);
            acc1b = fmaf(c - s, w, acc1b);
        }
    }

    g_partial[blockIdx.y][row0] = acc0 + acc0b;
    g_partial[blockIdx.y][row1] = acc1 + acc1b;
}

// ---------------------------------------------------------------------------
// Reduce partials, apply SIGMA*Ninv.
// ---------------------------------------------------------------------------
__global__ void __launch_bounds__(256)
reduce_kernel(float* __restrict__ out) {
    const int i = blockIdx.x * blockDim.x + threadIdx.x;
    float s = 0.0f;
    #pragma unroll
    for (int j = 0; j < NJS; j++) s += g_partial[j][i];
    out[i] = g_scale * s;
}

extern "C" void kernel_launch(void* const* d_in, const int* in_sizes, int n_in,
                              void* d_out, int out_size) {
    const float* pred = (const float*)d_in[0];
    const float* tgt  = (const float*)d_in[1];
    float* out        = (float*)d_out;

    prep_kernel<<<1, PREP_THREADS>>>(pred, tgt);
    dim3 grid(RB, NJS);
    pair_kernel<<<grid, PAIR_THREADS>>>();
    reduce_kernel<<<N / 256, 256>>>(out);
}

// round 2
// speedup vs baseline: 1.2914x; 1.2914x over previous
#include <cuda_runtime.h>

// LambdaRankLoss N=8192, 5 integer classes, SIGMA=1.
//
// lambda_i = scale * sum_j q_ij * r_ij * (g_j-g_i) * (d_i-d_j)
//   q = (g_j>g_i) ? e_i : -e_j,  r = 1/(e_i+e_j),  e=exp(p), g=2^t,
//   d = 1/log2(rank+1), scale = SIGMA/maxDCG.
// (g_j-g_i)(d_i-d_j) >= 0 always since rank order follows class order.

#define N        8192
#define NWARPS   (N / 32)        // 256
#define K_DCG    512
#define NJS      32
#define JTILE    (N / NJS)       // 256
#define PAIR_T   256
#define ROWS_BLK 512
#define RB       (N / ROWS_BLK)  // 16

__device__ float g_e[N];                 // exp(pred)
__device__ float g_g[N];                 // 2^target
__device__ float g_nd[N];                // NEGATED decay
__device__ int   g_wcnt[NWARPS][8];      // per-warp class counts (padded)
__device__ int   g_wpre[NWARPS][8];      // classbase + exclusive warp prefix
__device__ float g_scale;                // SIGMA / maxDCG
__device__ float g_partial[NJS][N];

// ---------------- packed f32x2 helpers (Blackwell) ----------------
__device__ __forceinline__ float2 f2add(float2 a, float2 b) {
    float2 c;
    asm("{\n\t.reg .b64 ra, rb, rc;\n\t"
        "mov.b64 ra, {%2, %3};\n\t"
        "mov.b64 rb, {%4, %5};\n\t"
        "add.rn.f32x2 rc, ra, rb;\n\t"
        "mov.b64 {%0, %1}, rc;\n\t}"
        : "=f"(c.x), "=f"(c.y)
        : "f"(a.x), "f"(a.y), "f"(b.x), "f"(b.y));
    return c;
}
__device__ __forceinline__ float2 f2mul(float2 a, float2 b) {
    float2 c;
    asm("{\n\t.reg .b64 ra, rb, rc;\n\t"
        "mov.b64 ra, {%2, %3};\n\t"
        "mov.b64 rb, {%4, %5};\n\t"
        "mul.rn.f32x2 rc, ra, rb;\n\t"
        "mov.b64 {%0, %1}, rc;\n\t}"
        : "=f"(c.x), "=f"(c.y)
        : "f"(a.x), "f"(a.y), "f"(b.x), "f"(b.y));
    return c;
}
__device__ __forceinline__ float2 f2fma(float2 a, float2 b, float2 c) {
    float2 d;
    asm("{\n\t.reg .b64 ra, rb, rc, rd;\n\t"
        "mov.b64 ra, {%2, %3};\n\t"
        "mov.b64 rb, {%4, %5};\n\t"
        "mov.b64 rc, {%6, %7};\n\t"
        "fma.rn.f32x2 rd, ra, rb, rc;\n\t"
        "mov.b64 {%0, %1}, rd;\n\t}"
        : "=f"(d.x), "=f"(d.y)
        : "f"(a.x), "f"(a.y), "f"(b.x), "f"(b.y), "f"(c.x), "f"(c.y));
    return d;
}
__device__ __forceinline__ float frcp(float x) {
    float r;
    asm("rcp.approx.f32 %0, %1;" : "=f"(r) : "f"(x));
    return r;
}

// ---------------- prep 1: e, g, per-warp class counts ----------------
__global__ void __launch_bounds__(256)
prep1(const float* __restrict__ pred, const float* __restrict__ tgt) {
    const int i    = blockIdx.x * 256 + threadIdx.x;
    const int lane = threadIdx.x & 31;
    const int gw   = i >> 5;

    float t = tgt[i];
    float p = pred[i];
    int v = (int)t;
    v = max(0, min(4, v));
    g_e[i] = __expf(p);
    g_g[i] = exp2f(t);

    #pragma unroll
    for (int c = 0; c < 5; c++) {
        unsigned b = __ballot_sync(0xffffffffu, v == c);
        if (lane == c) g_wcnt[gw][c] = __popc(b);
    }
}

// ---------------- prep 2: warp-prefix scan + maxDCG scale ----------------
__global__ void __launch_bounds__(512)
prep2() {
    __shared__ int   s[5][NWARPS];
    __shared__ int   s_tot[5];
    __shared__ int   s_base[5];
    __shared__ float s_red[512];

    const int t = threadIdx.x;
    int own[5] = {0, 0, 0, 0, 0};

    if (t < NWARPS) {
        #pragma unroll
        for (int v = 0; v < 5; v++) {
            own[v] = g_wcnt[t][v];
            s[v][t] = own[v];
        }
    }
    __syncthreads();

    // inclusive Hillis-Steele scan over 256 warps, per class
    for (int ofs = 1; ofs < NWARPS; ofs <<= 1) {
        int a[5] = {0, 0, 0, 0, 0};
        if (t < NWARPS && t >= ofs) {
            #pragma unroll
            for (int v = 0; v < 5; v++) a[v] = s[v][t - ofs];
        }
        __syncthreads();
        if (t < NWARPS) {
            #pragma unroll
            for (int v = 0; v < 5; v++) s[v][t] += a[v];
        }
        __syncthreads();
    }

    if (t == 0) {
        int run = 0;
        #pragma unroll
        for (int v = 0; v < 5; v++) {
            s_tot[v]  = s[v][NWARPS - 1];
            s_base[v] = run;
            run += s_tot[v];
        }
    }
    __syncthreads();

    if (t < NWARPS) {
        #pragma unroll
        for (int v = 0; v < 5; v++)
            g_wpre[t][v] = s_base[v] + s[v][t] - own[v];  // exclusive
    }

    // maxDCG: top K_DCG of descending-sorted targets
    {
        int k  = t + 1;                                   // 1..512
        int c4 = s_tot[4];
        int c3 = c4 + s_tot[3];
        int c2 = c3 + s_tot[2];
        int c1 = c2 + s_tot[1];
        int v  = (k <= c4) ? 4 : (k <= c3) ? 3 : (k <= c2) ? 2 : (k <= c1) ? 1 : 0;
        s_red[t] = (exp2f((float)v) - 1.0f) / log2f((float)k + 1.0f);
    }
    __syncthreads();
    for (int sh = 256; sh > 0; sh >>= 1) {
        if (t < sh) s_red[t] += s_red[t + sh];
        __syncthreads();
    }
    if (t == 0) g_scale = __fdividef(1.0f, s_red[0]);     // SIGMA = 1
}

// ---------------- prep 3: stable rank -> negated decay ----------------
__global__ void __launch_bounds__(256)
prep3(const float* __restrict__ tgt) {
    const int i    = blockIdx.x * 256 + threadIdx.x;
    const int lane = threadIdx.x & 31;
    const int gw   = i >> 5;

    int v = (int)tgt[i];
    v = max(0, min(4, v));

    int intra = 0;
    #pragma unroll
    for (int c = 0; c < 5; c++) {
        unsigned b = __ballot_sync(0xffffffffu, v == c);
        if (v == c) intra = __popc(b & ((1u << lane) - 1u));
    }
    int rank = g_wpre[gw][v] + intra + 1;
    g_nd[i] = -__fdividef(1.0f, log2f((float)rank + 1.0f));
}

// ---------------- pairwise: grid (RB, NJS), 2 rows/thread, 2 j/iter ----------------
__global__ void __launch_bounds__(PAIR_T)
pair_kernel() {
    const int t  = threadIdx.x;
    const int r0 = blockIdx.x * ROWS_BLK + t;
    const int r1 = r0 + PAIR_T;

    const float e0  = g_e[r0],  e1  = g_e[r1];
    const float gg0 = g_g[r0],  gg1 = g_g[r1];
    const float d0  = -g_nd[r0], d1 = -g_nd[r1];
    const float ne0 = -e0, ne1 = -e1;

    const float2 eaa0  = make_float2(e0, e0),     eaa1  = make_float2(e1, e1);
    const float2 ngaa0 = make_float2(-gg0, -gg0), ngaa1 = make_float2(-gg1, -gg1);
    const float2 daa0  = make_float2(d0, d0),     daa1  = make_float2(d1, d1);

    float2 acc0 = make_float2(0.f, 0.f);
    float2 acc1 = make_float2(0.f, 0.f);

    const int jbase = blockIdx.y * JTILE;
    const float2* __restrict__ pe  = (const float2*)(g_e  + jbase);
    const float2* __restrict__ pg  = (const float2*)(g_g  + jbase);
    const float2* __restrict__ pnd = (const float2*)(g_nd + jbase);

    #pragma unroll 4
    for (int j = 0; j < JTILE / 2; j++) {
        const float2 e2  = __ldg(pe + j);    // uniform across warp -> broadcast
        const float2 g2  = __ldg(pg + j);
        const float2 nd2 = __ldg(pnd + j);

        // row 0
        {
            float2 sum = f2add(eaa0, e2);
            float  ra  = frcp(sum.x);
            float  rb  = frcp(sum.y);
            float2 gd  = f2add(g2, ngaa0);
            float2 dd  = f2add(daa0, nd2);
            float2 w   = f2mul(gd, dd);
            float2 wr  = f2mul(w, make_float2(ra, rb));
            float2 q;
            q.x = (g2.x > gg0) ? e0 : -e2.x;
            q.y = (g2.y > gg0) ? e0 : -e2.y;
            acc0 = f2fma(q, wr, acc0);
        }
        // row 1
        {
            float2 sum = f2add(eaa1, e2);
            float  ra  = frcp(sum.x);
            float  rb  = frcp(sum.y);
            float2 gd  = f2add(g2, ngaa1);
            float2 dd  = f2add(daa1, nd2);
            float2 w   = f2mul(gd, dd);
            float2 wr  = f2mul(w, make_float2(ra, rb));
            float2 q;
            q.x = (g2.x > gg1) ? e1 : -e2.x;
            q.y = (g2.y > gg1) ? e1 : -e2.y;
            acc1 = f2fma(q, wr, acc1);
        }
        (void)ne0; (void)ne1;
    }

    g_partial[blockIdx.y][r0] = acc0.x + acc0.y;
    g_partial[blockIdx.y][r1] = acc1.x + acc1.y;
}

// ---------------- reduce partials + scale ----------------
__global__ void __launch_bounds__(256)
reduce_kernel(float* __restrict__ out) {
    const int i = blockIdx.x * 256 + threadIdx.x;
    float s = 0.0f;
    #pragma unroll
    for (int j = 0; j < NJS; j++) s += g_partial[j][i];
    out[i] = g_scale * s;
}

extern "C" void kernel_launch(void* const* d_in, const int* in_sizes, int n_in,
                              void* d_out, int out_size) {
    const float* pred = (const float*)d_in[0];
    const float* tgt  = (const float*)d_in[1];
    float* out        = (float*)d_out;

    prep1<<<N / 256, 256>>>(pred, tgt);
    prep2<<<1, 512>>>();
    prep3<<<N / 256, 256>>>(tgt);
    dim3 grid(RB, NJS);
    pair_kernel<<<grid, PAIR_T>>>();
    reduce_kernel<<<N / 256, 256>>>(out);
}

// round 3
// speedup vs baseline: 1.3963x; 1.0812x over previous
#include <cuda_runtime.h>

// LambdaRankLoss N=8192, 5 integer classes (0..4), SIGMA=1.
//
//   e_i = exp(p_i), g_i = 2^t_i, rank ascending-by-target (stable),
//   d_k = 1/log2(k+2) at sorted position k, G_c = 2^c.
//
//   lambda_i = scale * ( e_i * T1_i  -  T2_i )
//   T1_i = sum_j (g_j - g_i) * (d_i - d_j) / (e_i + e_j)      [all j]
//   T2_i = sum_{c < v_i} (G_c - g_i) * (n_c * d_i - SD_c)     [O(1)]
//   scale = SIGMA / maxDCG
//
// All arrays sorted by class (== rank order), so per class segment the
// (G_c - g_i) coefficient folds out of the inner loop:
//   inner loop/pair: FADD, MUFU.RCP, FADD, FFMA  -> MUFU-bound.
// Segments with c == v_i (coef 0) are skipped warp-uniformly.

#define N        8192
#define NWARPS   (N / 32)        // 256
#define K_DCG    512
#define NJS      32
#define JTILE    (N / NJS)       // 256
#define PAIR_T   128
#define ROWS_BLK 256
#define RB       (N / ROWS_BLK)  // 32

__device__ float2 g_sed[N];          // sorted (e, -decay)
__device__ int    g_inv[N];          // sorted pos -> original index
__device__ int    g_seg[8];          // class segment starts, g_seg[5] = N
__device__ float  g_SD[5];           // per-class sum of decay
__device__ float  g_scale;           // SIGMA / maxDCG
__device__ int    g_wcnt[NWARPS][8];
__device__ int    g_wpre[NWARPS][8];
__device__ float2 g_part[NJS][N / 2];

__device__ __forceinline__ float frcp(float x) {
    float r;
    asm("rcp.approx.f32 %0, %1;" : "=f"(r) : "f"(x));
    return r;
}

// ---------------- prep1: per-warp class counts ----------------
__global__ void __launch_bounds__(256)
prep1(const float* __restrict__ tgt) {
    const int i    = blockIdx.x * 256 + threadIdx.x;
    const int lane = threadIdx.x & 31;
    const int gw   = i >> 5;
    int v = (int)tgt[i];
    v = max(0, min(4, v));
    #pragma unroll
    for (int c = 0; c < 5; c++) {
        unsigned b = __ballot_sync(0xffffffffu, v == c);
        if (lane == c) g_wcnt[gw][c] = __popc(b);
    }
}

// ---------------- prep2: scan, segments, maxDCG, decay sums ----------------
__global__ void __launch_bounds__(512)
prep2() {
    __shared__ int   s[5][NWARPS];
    __shared__ int   s_tot[5];
    __shared__ int   s_base[8];
    __shared__ float s_red[512];
    __shared__ float s_sd[5][512];

    const int t = threadIdx.x;
    int own[5] = {0, 0, 0, 0, 0};

    if (t < NWARPS) {
        #pragma unroll
        for (int v = 0; v < 5; v++) { own[v] = g_wcnt[t][v]; s[v][t] = own[v]; }
    }
    __syncthreads();

    for (int ofs = 1; ofs < NWARPS; ofs <<= 1) {
        int a[5] = {0, 0, 0, 0, 0};
        if (t < NWARPS && t >= ofs) {
            #pragma unroll
            for (int v = 0; v < 5; v++) a[v] = s[v][t - ofs];
        }
        __syncthreads();
        if (t < NWARPS) {
            #pragma unroll
            for (int v = 0; v < 5; v++) s[v][t] += a[v];
        }
        __syncthreads();
    }

    if (t == 0) {
        int run = 0;
        #pragma unroll
        for (int v = 0; v < 5; v++) {
            s_tot[v]  = s[v][NWARPS - 1];
            s_base[v] = run;
            run += s_tot[v];
        }
        s_base[5] = N;
        #pragma unroll
        for (int v = 0; v < 6; v++) g_seg[v] = s_base[v];
    }
    __syncthreads();

    if (t < NWARPS) {
        #pragma unroll
        for (int v = 0; v < 5; v++)
            g_wpre[t][v] = s_base[v] + s[v][t] - own[v];   // exclusive prefix
    }

    // maxDCG (descending-sorted targets, top K_DCG)
    {
        int k  = t + 1;
        int c4 = s_tot[4];
        int c3 = c4 + s_tot[3];
        int c2 = c3 + s_tot[2];
        int c1 = c2 + s_tot[1];
        int v  = (k <= c4) ? 4 : (k <= c3) ? 3 : (k <= c2) ? 2 : (k <= c1) ? 1 : 0;
        s_red[t] = (exp2f((float)v) - 1.0f) / log2f((float)k + 1.0f);
    }

    // per-class decay sums: thread t handles ranks t*16+1 .. t*16+16
    {
        float loc[5] = {0.f, 0.f, 0.f, 0.f, 0.f};
        int b1 = s_base[1], b2 = s_base[2], b3 = s_base[3], b4 = s_base[4];
        #pragma unroll
        for (int k = 0; k < 16; k++) {
            int r   = t * 16 + k + 1;            // rank
            int pos = r - 1;
            int c   = (pos >= b1) + (pos >= b2) + (pos >= b3) + (pos >= b4);
            loc[c] += __fdividef(1.0f, log2f((float)r + 1.0f));
        }
        #pragma unroll
        for (int c = 0; c < 5; c++) s_sd[c][t] = loc[c];
    }
    __syncthreads();

    for (int sh = 256; sh > 0; sh >>= 1) {
        if (t < sh) {
            s_red[t] += s_red[t + sh];
            #pragma unroll
            for (int c = 0; c < 5; c++) s_sd[c][t] += s_sd[c][t + sh];
        }
        __syncthreads();
    }
    if (t == 0) {
        g_scale = __fdividef(1.0f, s_red[0]);    // SIGMA = 1
        #pragma unroll
        for (int c = 0; c < 5; c++) g_SD[c] = s_sd[c][0];
    }
}

// ---------------- prep3: scatter into sorted order ----------------
__global__ void __launch_bounds__(256)
prep3(const float* __restrict__ pred, const float* __restrict__ tgt) {
    const int i    = blockIdx.x * 256 + threadIdx.x;
    const int lane = threadIdx.x & 31;
    const int gw   = i >> 5;

    int v = (int)tgt[i];
    v = max(0, min(4, v));

    int intra = 0;
    #pragma unroll
    for (int c = 0; c < 5; c++) {
        unsigned b = __ballot_sync(0xffffffffu, v == c);
        if (v == c) intra = __popc(b & ((1u << lane) - 1u));
    }
    int k = g_wpre[gw][v] + intra;               // sorted position (rank-1)
    float e  = __expf(pred[i]);
    float nd = -__fdividef(1.0f, log2f((float)k + 2.0f));
    g_sed[k] = make_float2(e, nd);
    g_inv[k] = i;
}

// ---------------- pairwise: grid (RB, NJS), rows sorted, class segments ----
__global__ void __launch_bounds__(PAIR_T)
pair_kernel() {
    const int t  = threadIdx.x;
    const int r0 = blockIdx.x * ROWS_BLK + 2 * t;
    const int r1 = r0 + 1;

    int b1 = g_seg[1], b2 = g_seg[2], b3 = g_seg[3], b4 = g_seg[4];

    const float2 a0 = g_sed[r0];
    const float2 a1 = g_sed[r1];
    const float e0 = a0.x, d0 = -a0.y;
    const float e1 = a1.x, d1 = -a1.y;
    const int v0 = (r0 >= b1) + (r0 >= b2) + (r0 >= b3) + (r0 >= b4);
    const int v1 = (r1 >= b1) + (r1 >= b2) + (r1 >= b3) + (r1 >= b4);
    const float gi0 = (float)(1 << v0);
    const float gi1 = (float)(1 << v1);

    const int s0j = blockIdx.y * JTILE;
    const int s1j = s0j + JTILE;

    float acc0 = 0.0f, acc1 = 0.0f;

    #pragma unroll
    for (int c = 0; c < 5; c++) {
        const int lo = max(g_seg[c], s0j);
        const int hi = min(g_seg[c + 1], s1j);
        // whole-warp zero coefficient -> skip segment
        if (__all_sync(0xffffffffu, (c == v0) && (c == v1))) continue;

        float S0 = 0.0f, S1 = 0.0f;
        #pragma unroll 4
        for (int j = lo; j < hi; j++) {
            const float2 w = __ldg(&g_sed[j]);   // warp-uniform -> broadcast
            float s0 = e0 + w.x;
            float s1 = e1 + w.x;
            float dd0 = d0 + w.y;
            float dd1 = d1 + w.y;
            float rr0 = frcp(s0);
            float rr1 = frcp(s1);
            S0 = fmaf(rr0, dd0, S0);
            S1 = fmaf(rr1, dd1, S1);
        }
        const float Gc = (float)(1 << c);
        acc0 = fmaf(Gc - gi0, S0, acc0);
        acc1 = fmaf(Gc - gi1, S1, acc1);
    }

    g_part[blockIdx.y][(blockIdx.x * ROWS_BLK) / 2 + t] = make_float2(acc0, acc1);
}

// ---------------- reduce: T1 partials + analytic T2, scatter out ----------
__global__ void __launch_bounds__(256)
reduce_kernel(float* __restrict__ out) {
    const int k = blockIdx.x * 256 + threadIdx.x;   // sorted position

    float T1 = 0.0f;
    #pragma unroll
    for (int s = 0; s < NJS; s++)
        T1 += ((const float*)g_part[s])[k];

    int b1 = g_seg[1], b2 = g_seg[2], b3 = g_seg[3], b4 = g_seg[4];
    const int v = (k >= b1) + (k >= b2) + (k >= b3) + (k >= b4);

    const float2 a = g_sed[k];
    const float e = a.x;
    const float d = -a.y;
    const float g = (float)(1 << v);

    float T2 = 0.0f;
    #pragma unroll
    for (int c = 0; c < 4; c++) {
        if (c < v) {
            float nc = (float)(g_seg[c + 1] - g_seg[c]);
            T2 += ((float)(1 << c) - g) * (nc * d - g_SD[c]);
        }
    }

    out[g_inv[k]] = g_scale * (e * T1 - T2);
}

extern "C" void kernel_launch(void* const* d_in, const int* in_sizes, int n_in,
                              void* d_out, int out_size) {
    const float* pred = (const float*)d_in[0];
    const float* tgt  = (const float*)d_in[1];
    float* out        = (float*)d_out;

    prep1<<<N / 256, 256>>>(tgt);
    prep2<<<1, 512>>>();
    prep3<<<N / 256, 256>>>(pred, tgt);
    dim3 grid(RB, NJS);
    pair_kernel<<<grid, PAIR_T>>>();
    reduce_kernel<<<N / 256, 256>>>(out);
}